// round 11
// baseline (speedup 1.0000x reference)
#include <cuda_runtime.h>
#include <stdint.h>

// Lovasz-Softmax, N=8, C=19, H=W=512.
// R11: hist converted to a cp.async.bulk double-buffered smem pipeline:
// one elected thread bulk-copies the next tile (19 class rows + labels,
// 80KB) while all warps compute the current tile from smem. Removes the
// per-iteration LDG long-scoreboard stalls (R10: issue 49.5%, ~50% stalled).
// Consumer math bit-identical to R10. reduce/scan unchanged.

#define NCLS   19
#define NBINS  512
#define CUTBIN 128                 // drop bg entries with e < 1/4
#define HWSZ   (512 * 512)
#define NPIX   (8 * HWSZ)
#define NBLK   148
#define NTHR_H 512

#define TILE_PAIRS 512
#define ROW_B      4096            // 512 pairs * 8B
#define TILE_B     (20 * ROW_B)    // 19 class rows + 1 label row = 80KB
#define NTILES     (NPIX / 2 / TILE_PAIRS)   // 2048

#define HIST_WORDS (NCLS * NBINS + 64)        // 9792
#define HIST_B     (HIST_WORDS * 4)           // 39168 (128B-aligned)
#define BUF0_OFF   HIST_B
#define BUF1_OFF   (HIST_B + TILE_B)
#define SMEM_TOTAL (HIST_B + 2 * TILE_B)      // 203008

#define H_MAG  0x6600u             // fp16 bits of 1536.0 (1.5*2^10)
#define H_MAG2 0x66006600u
#define H_CUT  (0x6600u + CUTBIN)

#define F_L2E  1.4426950408889634f
#define F_MG   12582912.0f         // 1.5 * 2^23
#define F_C4   9.61812910e-3f
#define F_C3   5.55041087e-2f
#define F_C2   2.40226507e-1f
#define F_C1   6.93147181e-1f

typedef unsigned long long u64;

// Per-block partial histograms (packed cnt low16 | fg high16). 5.76 MB.
__device__ uint32_t g_part[NBLK * NCLS * NBINS];
__device__ uint32_t g_cnt[NCLS * NBINS];
__device__ uint32_t g_fg [NCLS * NBINS];

// ---- packed f32x2 helpers (PTX-only) ----
__device__ __forceinline__ u64 pk(float a, float b) {
    u64 r; asm("mov.b64 %0,{%1,%2};" : "=l"(r) : "f"(a), "f"(b)); return r;
}
__device__ __forceinline__ void upk(u64 v, float& a, float& b) {
    asm("mov.b64 {%0,%1},%2;" : "=f"(a), "=f"(b) : "l"(v));
}
__device__ __forceinline__ u64 f2fma(u64 a, u64 b, u64 c) {
    u64 r; asm("fma.rn.f32x2 %0,%1,%2,%3;" : "=l"(r) : "l"(a), "l"(b), "l"(c));
    return r;
}
__device__ __forceinline__ u64 dup2(float a) { return pk(a, a); }
__device__ __forceinline__ float rcp_fast(float x) {
    float r; asm("rcp.approx.f32 %0,%1;" : "=f"(r) : "f"(x)); return r;
}
__device__ __forceinline__ uint32_t s2u(const void* p) {
    uint32_t a;
    asm("{ .reg .u64 t; cvta.to.shared.u64 t, %1; cvt.u32.u64 %0, t; }"
        : "=r"(a) : "l"(p));
    return a;
}

// Scalar exp replicating the packed pipeline op-for-op (bit-identical f32).
__device__ __forceinline__ float exp_mirror(float x) {
    float fm = fmaf(x, F_L2E, F_MG);
    float nf = fmaf(fm, -1.0f, F_MG);
    float f  = fmaf(x, F_L2E, nf);
    float r  = fmaf(F_C4, f, F_C3);
    r = fmaf(r, f, F_C2);
    r = fmaf(r, f, F_C1);
    r = fmaf(r, f, 1.0f);
    return __int_as_float(__float_as_int(r) +
                          __float_as_int(fm) * 8388608);
}

__device__ __forceinline__ void mbar_init(uint32_t a, uint32_t cnt) {
    asm volatile("mbarrier.init.shared.b64 [%0], %1;" :: "r"(a), "r"(cnt)
                 : "memory");
}
__device__ __forceinline__ void mbar_expect(uint32_t a, uint32_t bytes) {
    asm volatile("mbarrier.arrive.expect_tx.shared.b64 _, [%0], %1;"
                 :: "r"(a), "r"(bytes) : "memory");
}
__device__ __forceinline__ void bulk_cp(uint32_t dst, const void* src,
                                        uint32_t bytes, uint32_t mbar) {
    asm volatile(
        "cp.async.bulk.shared::cta.global.mbarrier::complete_tx::bytes "
        "[%0], [%1], %2, [%3];"
        :: "r"(dst), "l"((u64)src), "r"(bytes), "r"(mbar) : "memory");
}
__device__ __forceinline__ void mbar_wait(uint32_t a, uint32_t parity) {
    asm volatile(
        "{\n\t"
        ".reg .pred P;\n\t"
        "W_%=:\n\t"
        "mbarrier.try_wait.parity.acquire.cta.shared::cta.b64 P, [%0], %1, 0x989680;\n\t"
        "@P bra.uni D_%=;\n\t"
        "bra.uni W_%=;\n\t"
        "D_%=:\n\t"
        "}"
        :: "r"(a), "r"(parity) : "memory");
}

extern __shared__ uint32_t sh[];   // hist | buf0 | buf1

__global__ __launch_bounds__(NTHR_H, 1) void hist_kernel(
    const float* __restrict__ logits, const int* __restrict__ labels,
    float* __restrict__ d_out) {
    __shared__ __align__(8) u64 mbars[2];
    int tid = threadIdx.x;
    char* smem = (char*)sh;
    uint32_t mb0 = s2u(&mbars[0]);
    uint32_t mb1 = s2u(&mbars[1]);
    uint32_t buf_u32[2] = { s2u(smem + BUF0_OFF), s2u(smem + BUF1_OFF) };

    if (blockIdx.x == 0 && tid == 0) *d_out = 0.0f;
    if (tid == 0) { mbar_init(mb0, 1); mbar_init(mb1, 1); }
    {
        uint4 z = make_uint4(0, 0, 0, 0);
        uint4* s4 = (uint4*)sh;
        for (int i = tid; i < HIST_WORDS / 4; i += NTHR_H) s4[i] = z;
    }
    __syncthreads();

    const u64 LOG2E = dup2(F_L2E);
    const u64 MG    = dup2(F_MG);
    const u64 NONE  = dup2(-1.0f);
    const u64 C4 = dup2(F_C4);
    const u64 C3 = dup2(F_C3);
    const u64 C2 = dup2(F_C2);
    const u64 C1 = dup2(F_C1);
    const u64 C0 = dup2(1.0f);
    const uint32_t MG16 = H_MAG2;
    const uint32_t mbar_a[2] = { mb0, mb1 };

    // Prologue: issue tile t0 into buf0 / mbar0.
    int t0 = blockIdx.x;
    if (tid == 0) {
        int n  = t0 >> 8;                      // (t0*1024) >> 18
        int hw = (t0 * 1024) & (HWSZ - 1);
        mbar_expect(mb0, TILE_B);
#pragma unroll
        for (int c = 0; c < NCLS; c++)
            bulk_cp(buf_u32[0] + c * ROW_B,
                    logits + ((size_t)n * NCLS + c) * HWSZ + hw, ROW_B, mb0);
        bulk_cp(buf_u32[0] + NCLS * ROW_B, labels + t0 * 1024, ROW_B, mb0);
    }

    int i = 0;
    for (int tl = t0; tl < NTILES; tl += NBLK, i++) {
        int b = i & 1;
        __syncthreads();                       // buf[b^1] fully consumed
        int nxt = tl + NBLK;
        if (tid == 0 && nxt < NTILES) {
            int n  = nxt >> 8;
            int hw = (nxt * 1024) & (HWSZ - 1);
            uint32_t db = buf_u32[b ^ 1];
            uint32_t mb = mbar_a[b ^ 1];
            mbar_expect(mb, TILE_B);
#pragma unroll
            for (int c = 0; c < NCLS; c++)
                bulk_cp(db + c * ROW_B,
                        logits + ((size_t)n * NCLS + c) * HWSZ + hw,
                        ROW_B, mb);
            bulk_cp(db + NCLS * ROW_B, labels + nxt * 1024, ROW_B, mb);
        }
        mbar_wait(mbar_a[b], (i >> 1) & 1);    // tile tl ready

        // ---- compute one pair from smem tile ----
        const u64* tile = (const u64*)(smem + (b ? BUF1_OFF : BUF0_OFF));
        uint32_t eb[NCLS];
        float sa = 0.0f, sb = 0.0f;
#pragma unroll
        for (int c = 0; c < NCLS; c++) {
            u64 xv = tile[c * TILE_PAIRS + tid];       // LDS.64
            u64 fm = f2fma(xv, LOG2E, MG);
            u64 nf = f2fma(fm, NONE, MG);              // -round(t)
            u64 f  = f2fma(xv, LOG2E, nf);
            u64 r  = f2fma(C4, f, C3);
            r = f2fma(r, f, C2);
            r = f2fma(r, f, C1);
            r = f2fma(r, f, C0);
            float fm0, fm1, r0, r1;
            upk(fm, fm0, fm1);
            upk(r, r0, r1);
            float e0 = __int_as_float(__float_as_int(r0) +
                                      __float_as_int(fm0) * 8388608);
            float e1 = __int_as_float(__float_as_int(r1) +
                                      __float_as_int(fm1) * 8388608);
            sa += e0;
            sb += e1;
            uint32_t w;
            asm("cvt.rn.f16x2.f32 %0,%1,%2;" : "=r"(w) : "f"(e1), "f"(e0));
            eb[c] = w;
        }
        float invNa = rcp_fast(sa) * (float)NBINS;
        float invNb = rcp_fast(sb) * (float)NBINS;
        uint32_t inv2;
        asm("cvt.rn.f16x2.f32 %0,%1,%2;" : "=r"(inv2) : "f"(invNb), "f"(invNa));
        int2 lab = ((const int2*)(tile + NCLS * TILE_PAIRS))[tid];

#pragma unroll
        for (int c = 0; c < NCLS; c++) {
            uint32_t b2;
            asm("fma.rn.f16x2 %0,%1,%2,%3;"
                : "=r"(b2) : "r"(eb[c]), "r"(inv2), "r"(MG16));
            uint32_t ra = b2 & 0xFFFFu;
            uint32_t rb = b2 >> 16;
            if (ra >= H_CUT)
                atomicAdd(&sh[c * NBINS + (ra - H_MAG)], 1u);
            if (rb >= H_CUT)
                atomicAdd(&sh[c * NBINS + (rb - H_MAG)], 1u);
        }

        // Label bins via smem gather + bit-exact scalar recompute.
        {
            float xa, xb, dumm;
            u64 va = tile[lab.x * TILE_PAIRS + tid];
            u64 vb = tile[lab.y * TILE_PAIRS + tid];
            upk(va, xa, dumm);                 // pixel a = lo
            upk(vb, dumm, xb);                 // pixel b = hi
            float ea  = exp_mirror(xa);
            float ebv = exp_mirror(xb);
            uint32_t el2;
            asm("cvt.rn.f16x2.f32 %0,%1,%2;" : "=r"(el2) : "f"(ebv), "f"(ea));
            uint32_t bl2;
            asm("fma.rn.f16x2 %0,%1,%2,%3;"
                : "=r"(bl2) : "r"(el2), "r"(inv2), "r"(MG16));
            uint32_t bax = bl2 & 0xFFFFu;
            uint32_t bay = bl2 >> 16;
            int bfx = min((int)(NBINS - (bax - H_MAG)), NBINS - 1);
            atomicAdd(&sh[lab.x * NBINS + bfx], 0x10001u);
            int bfy = min((int)(NBINS - (bay - H_MAG)), NBINS - 1);
            atomicAdd(&sh[lab.y * NBINS + bfy], 0x10001u);
        }
    }
    __syncthreads();

    uint4* dst = (uint4*)(g_part + (size_t)blockIdx.x * NCLS * NBINS);
    const uint4* src = (const uint4*)sh;
    for (int i2 = tid; i2 < NCLS * NBINS / 4; i2 += NTHR_H) dst[i2] = src[i2];
}

// Full-chip slice reduction: 152 blocks x 256 thr.
__global__ __launch_bounds__(256) void reduce_kernel() {
    int base = blockIdx.x * 64;
    int t = threadIdx.x;
    int bin = t & 63;
    int g   = t >> 6;                      // 0..3

    __shared__ uint32_t sc[64], sf[64];
    if (t < 64) { sc[t] = 0; sf[t] = 0; }
    __syncthreads();

    const uint32_t* p = g_part + base + bin;
    uint32_t cs = 0, fs = 0;
#pragma unroll 8
    for (int s = g * 37; s < g * 37 + 37; s++) {
        uint32_t v = __ldg(p + (size_t)s * (NCLS * NBINS));
        cs += v & 0xFFFFu;
        fs += v >> 16;
    }
    if (cs | fs) {
        atomicAdd(&sc[bin], cs);
        atomicAdd(&sf[bin], fs);
    }
    __syncthreads();
    if (t < 64) {
        g_cnt[base + t] = sc[t];
        g_fg [base + t] = sf[t];
    }
}

// One block per class, 512 threads: mirror-correct, warp-shuffle prefix
// scan over descending ranks, closed-form Lovasz contribution.
__global__ __launch_bounds__(512) void scan_kernel(float* __restrict__ d_out) {
    int t = threadIdx.x;
    int c = blockIdx.x;

    __shared__ uint32_t wc[16], wf[16];
    __shared__ float    s_red[16];
    __shared__ float    s_totf;

    int b = (NBINS - 1) - t;
    uint32_t n = g_cnt[c * NBINS + b];
    uint32_t f = g_fg [c * NBINS + b];
    if (b >= CUTBIN) n -= g_fg[c * NBINS + (NBINS - b)];

    uint32_t ic = n, fc = f;
    int lane = t & 31, warp = t >> 5;
#pragma unroll
    for (int d = 1; d < 32; d <<= 1) {
        uint32_t pc = __shfl_up_sync(0xffffffffu, ic, d);
        uint32_t pf = __shfl_up_sync(0xffffffffu, fc, d);
        if (lane >= d) { ic += pc; fc += pf; }
    }
    if (lane == 31) { wc[warp] = ic; wf[warp] = fc; }
    __syncthreads();

    if (t < 32) {
        uint32_t vc = (t < 16) ? wc[t] : 0;
        uint32_t vf = (t < 16) ? wf[t] : 0;
        uint32_t sc2 = vc, sf2 = vf;
#pragma unroll
        for (int d = 1; d < 32; d <<= 1) {
            uint32_t pc = __shfl_up_sync(0xffffffffu, sc2, d);
            uint32_t pf = __shfl_up_sync(0xffffffffu, sf2, d);
            if (t >= d) { sc2 += pc; sf2 += pf; }
        }
        if (t < 16) { wc[t] = sc2 - vc; wf[t] = sf2 - vf; }
        if (t == 15) s_totf = (float)sf2;
    }
    __syncthreads();

    float acc = 0.0f;
    if (n) {
        float gts = s_totf;
        float ccx = (float)(wc[warp] + (ic - n));
        float cfx = (float)(wf[warp] + (fc - f));
        float un0 = gts + ccx - cfx;
        float Jprev = (un0 > 0.0f) ? 1.0f - (gts - cfx) / un0 : 0.0f;
        float cci = ccx + (float)n;
        float cfi = cfx + (float)f;
        float un  = gts + cci - cfi;
        float J   = 1.0f - (gts - cfi) / un;
        acc = (float)b * (1.0f / (float)NBINS) * (J - Jprev);
    }

#pragma unroll
    for (int d = 16; d > 0; d >>= 1)
        acc += __shfl_down_sync(0xffffffffu, acc, d);
    if (lane == 0) s_red[warp] = acc;
    __syncthreads();
    if (t == 0) {
        float s = 0.0f;
#pragma unroll
        for (int i = 0; i < 16; i++) s += s_red[i];
        atomicAdd(d_out, s * (1.0f / (float)NCLS));
    }
}

extern "C" void kernel_launch(void* const* d_in, const int* in_sizes, int n_in,
                              void* d_out, int out_size) {
    const float* logits = (const float*)d_in[0];
    const int*   labels = (const int*)d_in[1];
    float* out = (float*)d_out;
    (void)in_sizes; (void)n_in; (void)out_size;

    static bool configured = false;
    if (!configured) {
        cudaFuncSetAttribute(hist_kernel,
                             cudaFuncAttributeMaxDynamicSharedMemorySize,
                             SMEM_TOTAL);
        configured = true;
    }

    hist_kernel<<<NBLK, NTHR_H, SMEM_TOTAL>>>(logits, labels, out);
    reduce_kernel<<<NCLS * NBINS / 64, 256>>>();
    scan_kernel<<<NCLS, 512>>>(out);
}